// round 2
// baseline (speedup 1.0000x reference)
#include <cuda_runtime.h>
#include <math.h>
#include <float.h>

#define BB 2
#define LL 4096
#define DD 768
#define HH 12
#define DH 64
#define QKV_N (3*DD)

// Scratch (no cudaMalloc allowed): qkv activations and attention output.
__device__ float g_qkv[(size_t)BB * LL * QKV_N];   // ~75.5 MB
__device__ float g_y[(size_t)BB * LL * DD];        // ~25 MB

// ---------------------------------------------------------------------------
// C[M,N] = A[M,K] @ W[K,N] + bias[N]
// 64x64 block tile, BK=16, 256 threads, 4x4 microtile per thread.
// Requires M%64==0, N%64==0, K%16==0 (true for all our shapes).
// ---------------------------------------------------------------------------
__global__ __launch_bounds__(256) void sgemm_bias(
    const float* __restrict__ A, const float* __restrict__ W,
    const float* __restrict__ bias, float* __restrict__ C,
    int M, int N, int K)
{
    __shared__ float As[16][64];   // As[k][m]
    __shared__ float Ws[16][64];   // Ws[k][n]

    const int tid = threadIdx.x;
    const int ty = tid >> 4;        // 0..15
    const int tx = tid & 15;        // 0..15
    const int m0 = blockIdx.y * 64;
    const int n0 = blockIdx.x * 64;

    // loader mapping
    const int a_m  = tid >> 2;          // 0..63
    const int a_k4 = (tid & 3) * 4;     // 0,4,8,12
    const int w_k  = tid >> 4;          // 0..15
    const int w_n4 = (tid & 15) * 4;    // 0..60

    float acc[4][4] = {};

    for (int k0 = 0; k0 < K; k0 += 16) {
        float4 av = *(const float4*)(A + (size_t)(m0 + a_m) * K + k0 + a_k4);
        As[a_k4 + 0][a_m] = av.x;
        As[a_k4 + 1][a_m] = av.y;
        As[a_k4 + 2][a_m] = av.z;
        As[a_k4 + 3][a_m] = av.w;
        *(float4*)&Ws[w_k][w_n4] =
            *(const float4*)(W + (size_t)(k0 + w_k) * N + n0 + w_n4);
        __syncthreads();

        #pragma unroll
        for (int k = 0; k < 16; k++) {
            float ar[4], br[4];
            #pragma unroll
            for (int i = 0; i < 4; i++) ar[i] = As[k][ty * 4 + i];
            #pragma unroll
            for (int j = 0; j < 4; j++) br[j] = Ws[k][tx * 4 + j];
            #pragma unroll
            for (int i = 0; i < 4; i++)
                #pragma unroll
                for (int j = 0; j < 4; j++)
                    acc[i][j] = fmaf(ar[i], br[j], acc[i][j]);
        }
        __syncthreads();
    }

    #pragma unroll
    for (int i = 0; i < 4; i++) {
        const int row = m0 + ty * 4 + i;
        #pragma unroll
        for (int j = 0; j < 4; j++) {
            const int col = n0 + tx * 4 + j;
            C[(size_t)row * N + col] = acc[i][j] + bias[col];
        }
    }
}

// ---------------------------------------------------------------------------
// Fused causal flash attention, fp32.
// Grid: (L/64, H, B). Block: 256 threads (16x16), 4x4 microtiles.
// Q tile 64 rows, K/V tiles 64 cols; only tiles kt<=qt processed.
// smem: Qs (16KB) + KP (16KB, K-transposed then P) + Vs (16KB) = 48KB.
// ---------------------------------------------------------------------------
__global__ __launch_bounds__(256) void flash_attn(
    const float* __restrict__ qkv, float* __restrict__ y)
{
    __shared__ float Qs[64][64];   // Qs[row][d]
    __shared__ float KP[64][64];   // first K transposed: KP[d][col]; then P[row][col]
    __shared__ float Vs[64][64];   // Vs[col][d]

    const int tid = threadIdx.x;
    const int ty = tid >> 4;
    const int tx = tid & 15;
    const int qt = blockIdx.x;
    const int h  = blockIdx.y;
    const int b  = blockIdx.z;

    const size_t batch_off = (size_t)b * LL * QKV_N;
    const float* __restrict__ Qg = qkv + batch_off + h * DH;
    const float* __restrict__ Kg = qkv + batch_off + DD + h * DH;
    const float* __restrict__ Vg = qkv + batch_off + 2 * DD + h * DH;

    const int qbase = qt * 64;

    // Load Q tile (64x64) once.
    #pragma unroll
    for (int r = 0; r < 4; r++) {
        const int idx = tid + r * 256;
        const int row = idx >> 4;
        const int c4  = (idx & 15) * 4;
        *(float4*)&Qs[row][c4] =
            *(const float4*)(Qg + (size_t)(qbase + row) * QKV_N + c4);
    }

    float o[4][4] = {};
    float mrow[4] = {-FLT_MAX, -FLT_MAX, -FLT_MAX, -FLT_MAX};
    float lrow[4] = {0.f, 0.f, 0.f, 0.f};

    for (int kt = 0; kt <= qt; kt++) {
        const int kbase = kt * 64;

        // Load K (transposed into KP[d][col]) and V (Vs[col][d]).
        #pragma unroll
        for (int r = 0; r < 4; r++) {
            const int idx = tid + r * 256;
            const int col = idx >> 4;
            const int d4  = (idx & 15) * 4;
            float4 kv = *(const float4*)(Kg + (size_t)(kbase + col) * QKV_N + d4);
            KP[d4 + 0][col] = kv.x;
            KP[d4 + 1][col] = kv.y;
            KP[d4 + 2][col] = kv.z;
            KP[d4 + 3][col] = kv.w;
            *(float4*)&Vs[col][d4] =
                *(const float4*)(Vg + (size_t)(kbase + col) * QKV_N + d4);
        }
        __syncthreads();

        // S = Q @ K^T (4x4 per thread)
        float s[4][4] = {};
        #pragma unroll 8
        for (int d = 0; d < 64; d++) {
            float qr[4], kr[4];
            #pragma unroll
            for (int i = 0; i < 4; i++) qr[i] = Qs[ty * 4 + i][d];
            #pragma unroll
            for (int j = 0; j < 4; j++) kr[j] = KP[d][tx * 4 + j];
            #pragma unroll
            for (int i = 0; i < 4; i++)
                #pragma unroll
                for (int j = 0; j < 4; j++)
                    s[i][j] = fmaf(qr[i], kr[j], s[i][j]);
        }

        // scale + causal mask (only diagonal tile needs masking)
        if (kt == qt) {
            #pragma unroll
            for (int i = 0; i < 4; i++)
                #pragma unroll
                for (int j = 0; j < 4; j++) {
                    s[i][j] *= 0.125f;
                    if (kbase + tx * 4 + j > qbase + ty * 4 + i)
                        s[i][j] = -FLT_MAX;
                }
        } else {
            #pragma unroll
            for (int i = 0; i < 4; i++)
                #pragma unroll
                for (int j = 0; j < 4; j++) s[i][j] *= 0.125f;
        }

        // online softmax: row groups are 16 consecutive lanes (16-aligned).
        float mt[4], lt[4], alpha[4];
        #pragma unroll
        for (int i = 0; i < 4; i++) {
            float m = fmaxf(fmaxf(s[i][0], s[i][1]), fmaxf(s[i][2], s[i][3]));
            #pragma unroll
            for (int off = 8; off >= 1; off >>= 1)
                m = fmaxf(m, __shfl_xor_sync(0xffffffffu, m, off));
            mt[i] = m;
        }
        #pragma unroll
        for (int i = 0; i < 4; i++) {
            const float mn = fmaxf(mrow[i], mt[i]);
            alpha[i] = __expf(mrow[i] - mn);
            mrow[i] = mn;
        }
        #pragma unroll
        for (int i = 0; i < 4; i++) {
            float sum = 0.f;
            #pragma unroll
            for (int j = 0; j < 4; j++) {
                s[i][j] = __expf(s[i][j] - mrow[i]);  // s now holds P
                sum += s[i][j];
            }
            #pragma unroll
            for (int off = 8; off >= 1; off >>= 1)
                sum += __shfl_xor_sync(0xffffffffu, sum, off);
            lt[i] = sum;
        }
        #pragma unroll
        for (int i = 0; i < 4; i++) {
            lrow[i] = lrow[i] * alpha[i] + lt[i];
            #pragma unroll
            for (int j = 0; j < 4; j++) o[i][j] *= alpha[i];
        }

        __syncthreads();   // everyone done reading KP as K
        #pragma unroll
        for (int i = 0; i < 4; i++)
            #pragma unroll
            for (int j = 0; j < 4; j++)
                KP[ty * 4 + i][tx * 4 + j] = s[i][j];
        __syncthreads();

        // O += P @ V
        #pragma unroll 8
        for (int c = 0; c < 64; c++) {
            float pr[4], vr[4];
            #pragma unroll
            for (int i = 0; i < 4; i++) pr[i] = KP[ty * 4 + i][c];
            #pragma unroll
            for (int j = 0; j < 4; j++) vr[j] = Vs[c][tx * 4 + j];
            #pragma unroll
            for (int i = 0; i < 4; i++)
                #pragma unroll
                for (int j = 0; j < 4; j++)
                    o[i][j] = fmaf(pr[i], vr[j], o[i][j]);
        }
        __syncthreads();   // before next tile overwrites KP/Vs
    }

    // write y[b, row, h*64 + d] = o / l
    #pragma unroll
    for (int i = 0; i < 4; i++) {
        const float inv = 1.0f / lrow[i];
        const int row = qbase + ty * 4 + i;
        float4 v;
        v.x = o[i][0] * inv;
        v.y = o[i][1] * inv;
        v.z = o[i][2] * inv;
        v.w = o[i][3] * inv;
        *(float4*)(y + ((size_t)b * LL + row) * DD + h * DH + tx * 4) = v;
    }
}

// ---------------------------------------------------------------------------
extern "C" void kernel_launch(void* const* d_in, const int* in_sizes, int n_in,
                              void* d_out, int out_size)
{
    (void)in_sizes; (void)n_in; (void)out_size;
    const float* x    = (const float*)d_in[0];
    const float* Wqkv = (const float*)d_in[1];
    const float* bqkv = (const float*)d_in[2];
    const float* Wo   = (const float*)d_in[3];
    const float* bo   = (const float*)d_in[4];
    float* out = (float*)d_out;

    float *qkv_buf, *y_buf;
    cudaGetSymbolAddress((void**)&qkv_buf, g_qkv);
    cudaGetSymbolAddress((void**)&y_buf, g_y);

    const int M = BB * LL;  // 8192

    dim3 g1(QKV_N / 64, M / 64);
    sgemm_bias<<<g1, 256>>>(x, Wqkv, bqkv, qkv_buf, M, QKV_N, DD);

    dim3 g2(LL / 64, HH, BB);
    flash_attn<<<g2, 256>>>(qkv_buf, y_buf);

    dim3 g3(DD / 64, M / 64);
    sgemm_bias<<<g3, 256>>>(y_buf, Wo, bo, out, M, DD, DD);
}

// round 3
// speedup vs baseline: 3.7024x; 3.7024x over previous
#include <cuda_runtime.h>
#include <math.h>
#include <float.h>
#include <stdint.h>

#define BB 2
#define LL 4096
#define DD 768
#define HH 12
#define DH 64
#define QKV_N (3*DD)

// Scratch (no cudaMalloc allowed)
__device__ float g_qkv[(size_t)BB * LL * QKV_N];   // ~75.5 MB
__device__ float g_y[(size_t)BB * LL * DD];        // ~25 MB

__device__ __forceinline__ uint32_t f2tf(float x) {
    uint32_t r;
    asm("cvt.rna.tf32.f32 %0, %1;" : "=r"(r) : "f"(x));
    return r;
}

// D += A(16x8) * B(8x8), tf32, fp32 accumulate
__device__ __forceinline__ void mma8(float* d, const uint32_t* a, const uint32_t* b) {
    asm volatile(
        "mma.sync.aligned.m16n8k8.row.col.f32.tf32.tf32.f32 "
        "{%0,%1,%2,%3}, {%4,%5,%6,%7}, {%8,%9}, {%0,%1,%2,%3};"
        : "+f"(d[0]), "+f"(d[1]), "+f"(d[2]), "+f"(d[3])
        : "r"(a[0]), "r"(a[1]), "r"(a[2]), "r"(a[3]), "r"(b[0]), "r"(b[1]));
}

// ---------------------------------------------------------------------------
// C[M,N] = A[M,K] @ W[K,N] + bias, tf32 mma. BM=128, BN=128, BK=32.
// 256 threads = 8 warps (2x4), warp tile 64x32.
// As[m][k] stride 36 (≡4 mod 32: conflict-free A-frag reads)
// Bs[k][n] stride 136 (≡8 mod 32: conflict-free B-frag reads)
// ---------------------------------------------------------------------------
#define AS_S 36
#define BS_S 136

__global__ __launch_bounds__(256) void gemm_tf32(
    const float* __restrict__ A, const float* __restrict__ W,
    const float* __restrict__ bias, float* __restrict__ C,
    int M, int N, int K)
{
    __shared__ uint32_t As[128 * AS_S];
    __shared__ uint32_t Bs[32 * BS_S];

    const int tid = threadIdx.x;
    const int warp = tid >> 5, lane = tid & 31;
    const int g = lane >> 2, t = lane & 3;
    const int wm = (warp >> 2) * 64;   // 0 or 64
    const int wn = (warp & 3) * 32;    // 0..96
    const int m0 = blockIdx.y * 128;
    const int n0 = blockIdx.x * 128;

    float acc[4][4][4] = {};

    for (int k0 = 0; k0 < K; k0 += 32) {
        #pragma unroll
        for (int p = 0; p < 4; p++) {
            const int idx = p * 256 + tid;
            // A: 128 rows x 8 float4-chunks
            const int ar = idx >> 3, ac = (idx & 7) * 4;
            float4 av = *(const float4*)(A + (size_t)(m0 + ar) * K + k0 + ac);
            As[ar * AS_S + ac + 0] = f2tf(av.x);
            As[ar * AS_S + ac + 1] = f2tf(av.y);
            As[ar * AS_S + ac + 2] = f2tf(av.z);
            As[ar * AS_S + ac + 3] = f2tf(av.w);
            // B: 32 rows x 32 float4-chunks
            const int bk = idx >> 5, bc = (idx & 31) * 4;
            float4 wv = *(const float4*)(W + (size_t)(k0 + bk) * N + n0 + bc);
            Bs[bk * BS_S + bc + 0] = f2tf(wv.x);
            Bs[bk * BS_S + bc + 1] = f2tf(wv.y);
            Bs[bk * BS_S + bc + 2] = f2tf(wv.z);
            Bs[bk * BS_S + bc + 3] = f2tf(wv.w);
        }
        __syncthreads();

        #pragma unroll
        for (int kk = 0; kk < 32; kk += 8) {
            uint32_t af[4][4];
            #pragma unroll
            for (int mi = 0; mi < 4; mi++) {
                const int row = wm + mi * 16;
                af[mi][0] = As[(row + g) * AS_S + kk + t];
                af[mi][1] = As[(row + g + 8) * AS_S + kk + t];
                af[mi][2] = As[(row + g) * AS_S + kk + t + 4];
                af[mi][3] = As[(row + g + 8) * AS_S + kk + t + 4];
            }
            #pragma unroll
            for (int ni = 0; ni < 4; ni++) {
                uint32_t bf[2];
                const int coln = wn + ni * 8;
                bf[0] = Bs[(kk + t) * BS_S + coln + g];
                bf[1] = Bs[(kk + t + 4) * BS_S + coln + g];
                #pragma unroll
                for (int mi = 0; mi < 4; mi++) mma8(acc[mi][ni], af[mi], bf);
            }
        }
        __syncthreads();
    }

    #pragma unroll
    for (int mi = 0; mi < 4; mi++) {
        const int row = m0 + wm + mi * 16 + g;
        #pragma unroll
        for (int ni = 0; ni < 4; ni++) {
            const int col = n0 + wn + ni * 8 + 2 * t;
            const float bx = bias[col], by = bias[col + 1];
            float2 v0 = make_float2(acc[mi][ni][0] + bx, acc[mi][ni][1] + by);
            float2 v1 = make_float2(acc[mi][ni][2] + bx, acc[mi][ni][3] + by);
            *(float2*)(C + (size_t)row * N + col) = v0;
            *(float2*)(C + (size_t)(row + 8) * N + col) = v1;
        }
    }
}

// ---------------------------------------------------------------------------
// Fused causal flash attention, tf32 mma, fp32 softmax.
// Grid (L/64, H, B), 128 threads = 4 warps, each warp 16 q-rows.
// Q frags live in registers (scaled by 1/8). KP buffer holds K then P.
// KP stride 68 (≡4: A/B-frag reads with g-indexed rows), Vs stride 72 (≡8:
// B-frag reads with t-indexed rows) -> all conflict-free, no smem transposes.
// ---------------------------------------------------------------------------
__global__ __launch_bounds__(128) void flash_tf32(
    const float* __restrict__ qkv, float* __restrict__ y)
{
    __shared__ uint32_t KP[64 * 68];
    __shared__ uint32_t Vs[64 * 72];

    const int tid = threadIdx.x;
    const int warp = tid >> 5, lane = tid & 31;
    const int g = lane >> 2, t = lane & 3;
    const int qt = (int)gridDim.x - 1 - (int)blockIdx.x;  // big tiles first
    const int h = blockIdx.y, b = blockIdx.z;

    const size_t boff = (size_t)b * LL * QKV_N;
    const float* __restrict__ Qg = qkv + boff + h * DH;
    const float* __restrict__ Kg = qkv + boff + DD + h * DH;
    const float* __restrict__ Vg = qkv + boff + 2 * DD + h * DH;

    const int qbase = qt * 64;
    const int wrow = warp * 16;

    // Stage Q (pre-scaled by 1/8) via KP, then lift fragments to registers.
    #pragma unroll
    for (int p = 0; p < 8; p++) {
        const int idx = p * 128 + tid;
        const int r = idx >> 4, c = (idx & 15) * 4;
        float4 v = *(const float4*)(Qg + (size_t)(qbase + r) * QKV_N + c);
        KP[r * 68 + c + 0] = f2tf(v.x * 0.125f);
        KP[r * 68 + c + 1] = f2tf(v.y * 0.125f);
        KP[r * 68 + c + 2] = f2tf(v.z * 0.125f);
        KP[r * 68 + c + 3] = f2tf(v.w * 0.125f);
    }
    __syncthreads();
    uint32_t qf[8][4];
    #pragma unroll
    for (int k8 = 0; k8 < 8; k8++) {
        const int kk = k8 * 8;
        qf[k8][0] = KP[(wrow + g) * 68 + kk + t];
        qf[k8][1] = KP[(wrow + g + 8) * 68 + kk + t];
        qf[k8][2] = KP[(wrow + g) * 68 + kk + t + 4];
        qf[k8][3] = KP[(wrow + g + 8) * 68 + kk + t + 4];
    }
    __syncthreads();

    float o[8][4] = {};
    float m_lo = -FLT_MAX, m_hi = -FLT_MAX, l_lo = 0.f, l_hi = 0.f;

    for (int kt = 0; kt <= qt; kt++) {
        const int kbase = kt * 64;

        // Load K -> KP[seq][dh], V -> Vs[seq][dh] (coalesced, direct copy)
        #pragma unroll
        for (int p = 0; p < 8; p++) {
            const int idx = p * 128 + tid;
            const int r = idx >> 4, c = (idx & 15) * 4;
            float4 kv = *(const float4*)(Kg + (size_t)(kbase + r) * QKV_N + c);
            KP[r * 68 + c + 0] = f2tf(kv.x);
            KP[r * 68 + c + 1] = f2tf(kv.y);
            KP[r * 68 + c + 2] = f2tf(kv.z);
            KP[r * 68 + c + 3] = f2tf(kv.w);
            float4 vv = *(const float4*)(Vg + (size_t)(kbase + r) * QKV_N + c);
            Vs[r * 72 + c + 0] = f2tf(vv.x);
            Vs[r * 72 + c + 1] = f2tf(vv.y);
            Vs[r * 72 + c + 2] = f2tf(vv.z);
            Vs[r * 72 + c + 3] = f2tf(vv.w);
        }
        __syncthreads();

        // S = Q @ K^T : B-frag element (k=dh, n=seq) = KP[n][k]
        float s[8][4] = {};
        #pragma unroll
        for (int k8 = 0; k8 < 8; k8++) {
            const int kk = k8 * 8;
            #pragma unroll
            for (int n = 0; n < 8; n++) {
                uint32_t bf[2];
                bf[0] = KP[(n * 8 + g) * 68 + kk + t];
                bf[1] = KP[(n * 8 + g) * 68 + kk + t + 4];
                mma8(s[n], qf[k8], bf);
            }
        }

        // causal mask (diagonal tile only)
        if (kt == qt) {
            const int row_lo = qbase + wrow + g;
            const int row_hi = row_lo + 8;
            #pragma unroll
            for (int n = 0; n < 8; n++) {
                const int c0 = kbase + n * 8 + 2 * t;
                if (c0 > row_lo)     s[n][0] = -FLT_MAX;
                if (c0 + 1 > row_lo) s[n][1] = -FLT_MAX;
                if (c0 > row_hi)     s[n][2] = -FLT_MAX;
                if (c0 + 1 > row_hi) s[n][3] = -FLT_MAX;
            }
        }

        // online softmax (rows owned by quads: lanes 4g..4g+3)
        float mt_lo = -FLT_MAX, mt_hi = -FLT_MAX;
        #pragma unroll
        for (int n = 0; n < 8; n++) {
            mt_lo = fmaxf(mt_lo, fmaxf(s[n][0], s[n][1]));
            mt_hi = fmaxf(mt_hi, fmaxf(s[n][2], s[n][3]));
        }
        mt_lo = fmaxf(mt_lo, __shfl_xor_sync(0xffffffffu, mt_lo, 1));
        mt_lo = fmaxf(mt_lo, __shfl_xor_sync(0xffffffffu, mt_lo, 2));
        mt_hi = fmaxf(mt_hi, __shfl_xor_sync(0xffffffffu, mt_hi, 1));
        mt_hi = fmaxf(mt_hi, __shfl_xor_sync(0xffffffffu, mt_hi, 2));

        const float mn_lo = fmaxf(m_lo, mt_lo);
        const float mn_hi = fmaxf(m_hi, mt_hi);
        const float a_lo = __expf(m_lo - mn_lo);
        const float a_hi = __expf(m_hi - mn_hi);
        m_lo = mn_lo; m_hi = mn_hi;

        float sum_lo = 0.f, sum_hi = 0.f;
        #pragma unroll
        for (int n = 0; n < 8; n++) {
            s[n][0] = __expf(s[n][0] - m_lo);
            s[n][1] = __expf(s[n][1] - m_lo);
            s[n][2] = __expf(s[n][2] - m_hi);
            s[n][3] = __expf(s[n][3] - m_hi);
            sum_lo += s[n][0] + s[n][1];
            sum_hi += s[n][2] + s[n][3];
        }
        sum_lo += __shfl_xor_sync(0xffffffffu, sum_lo, 1);
        sum_lo += __shfl_xor_sync(0xffffffffu, sum_lo, 2);
        sum_hi += __shfl_xor_sync(0xffffffffu, sum_hi, 1);
        sum_hi += __shfl_xor_sync(0xffffffffu, sum_hi, 2);
        l_lo = l_lo * a_lo + sum_lo;
        l_hi = l_hi * a_hi + sum_hi;

        #pragma unroll
        for (int n = 0; n < 8; n++) {
            o[n][0] *= a_lo; o[n][1] *= a_lo;
            o[n][2] *= a_hi; o[n][3] *= a_hi;
        }

        __syncthreads();   // all warps done reading K from KP

        // write P -> KP[m][seq]
        #pragma unroll
        for (int n = 0; n < 8; n++) {
            const int c0 = n * 8 + 2 * t;
            KP[(wrow + g) * 68 + c0]         = f2tf(s[n][0]);
            KP[(wrow + g) * 68 + c0 + 1]     = f2tf(s[n][1]);
            KP[(wrow + g + 8) * 68 + c0]     = f2tf(s[n][2]);
            KP[(wrow + g + 8) * 68 + c0 + 1] = f2tf(s[n][3]);
        }
        __syncthreads();

        // O += P @ V : A-frag from KP rows (own 16), B-frag (k=seq,n=dh)=Vs[k][n]
        #pragma unroll
        for (int k8 = 0; k8 < 8; k8++) {
            const int kk = k8 * 8;
            uint32_t af[4];
            af[0] = KP[(wrow + g) * 68 + kk + t];
            af[1] = KP[(wrow + g + 8) * 68 + kk + t];
            af[2] = KP[(wrow + g) * 68 + kk + t + 4];
            af[3] = KP[(wrow + g + 8) * 68 + kk + t + 4];
            #pragma unroll
            for (int n = 0; n < 8; n++) {
                uint32_t bf[2];
                bf[0] = Vs[(kk + t) * 72 + n * 8 + g];
                bf[1] = Vs[(kk + t + 4) * 72 + n * 8 + g];
                mma8(o[n], af, bf);
            }
        }
        __syncthreads();   // before next kt overwrites KP/Vs
    }

    // O /= l, write out
    const float il_lo = 1.0f / l_lo;
    const float il_hi = 1.0f / l_hi;
    const int row_lo = qbase + wrow + g;
    #pragma unroll
    for (int n = 0; n < 8; n++) {
        const int col = h * DH + n * 8 + 2 * t;
        float2 v0 = make_float2(o[n][0] * il_lo, o[n][1] * il_lo);
        float2 v1 = make_float2(o[n][2] * il_hi, o[n][3] * il_hi);
        *(float2*)(y + ((size_t)b * LL + row_lo) * DD + col) = v0;
        *(float2*)(y + ((size_t)b * LL + row_lo + 8) * DD + col) = v1;
    }
}

// ---------------------------------------------------------------------------
extern "C" void kernel_launch(void* const* d_in, const int* in_sizes, int n_in,
                              void* d_out, int out_size)
{
    (void)in_sizes; (void)n_in; (void)out_size;
    const float* x    = (const float*)d_in[0];
    const float* Wqkv = (const float*)d_in[1];
    const float* bqkv = (const float*)d_in[2];
    const float* Wo   = (const float*)d_in[3];
    const float* bo   = (const float*)d_in[4];
    float* out = (float*)d_out;

    float *qkv_buf, *y_buf;
    cudaGetSymbolAddress((void**)&qkv_buf, g_qkv);
    cudaGetSymbolAddress((void**)&y_buf, g_y);

    const int M = BB * LL;  // 8192

    dim3 g1(QKV_N / 128, M / 128);
    gemm_tf32<<<g1, 256>>>(x, Wqkv, bqkv, qkv_buf, M, QKV_N, DD);

    dim3 g2(LL / 64, HH, BB);
    flash_tf32<<<g2, 128>>>(qkv_buf, y_buf);

    dim3 g3(DD / 128, M / 128);
    gemm_tf32<<<g3, 256>>>(y_buf, Wo, bo, out, M, DD, DD);
}

// round 5
// speedup vs baseline: 7.8937x; 2.1320x over previous
#include <cuda_runtime.h>
#include <cuda_fp16.h>
#include <math.h>
#include <float.h>
#include <stdint.h>

#define BB 2
#define LL 4096
#define DD 768
#define HH 12
#define DH 64
#define QKV_N (3*DD)
#define MM (BB*LL)

// Scratch (no cudaMalloc allowed)
__device__ __half g_xh[(size_t)MM * DD];        // 12.6 MB
__device__ __half g_wqkvt[(size_t)QKV_N * DD];  // 3.5 MB  (Wqkv^T, [N][K])
__device__ __half g_wot[(size_t)DD * DD];       // 1.2 MB  (Wo^T)
__device__ __half g_qkvh[(size_t)MM * QKV_N];   // 37.7 MB (q pre-scaled)
__device__ __half g_yh[(size_t)MM * DD];        // 12.6 MB

// ---------------------------------------------------------------------------
// helpers
// ---------------------------------------------------------------------------
__device__ __forceinline__ uint32_t smem_u32(const void* p) {
    uint32_t a;
    asm("{ .reg .u64 t; cvta.to.shared.u64 t, %1; cvt.u32.u64 %0, t; }"
        : "=r"(a) : "l"(p));
    return a;
}
__device__ __forceinline__ void cp16(uint32_t dst, const void* src) {
    asm volatile("cp.async.cg.shared.global [%0], [%1], 16;"
                 :: "r"(dst), "l"(src));
}
#define CP_COMMIT asm volatile("cp.async.commit_group;" ::: "memory")
#define CP_WAIT0  asm volatile("cp.async.wait_group 0;" ::: "memory")

__device__ __forceinline__ void ldsm4(uint32_t* r, uint32_t a) {
    asm volatile("ldmatrix.sync.aligned.m8n8.x4.shared.b16 {%0,%1,%2,%3}, [%4];"
        : "=r"(r[0]), "=r"(r[1]), "=r"(r[2]), "=r"(r[3]) : "r"(a));
}
__device__ __forceinline__ void ldsm4t(uint32_t* r, uint32_t a) {
    asm volatile("ldmatrix.sync.aligned.m8n8.x4.trans.shared.b16 {%0,%1,%2,%3}, [%4];"
        : "=r"(r[0]), "=r"(r[1]), "=r"(r[2]), "=r"(r[3]) : "r"(a));
}
__device__ __forceinline__ void mma16(float* d, const uint32_t* a,
                                      uint32_t b0, uint32_t b1) {
    asm volatile(
        "mma.sync.aligned.m16n8k16.row.col.f32.f16.f16.f32 "
        "{%0,%1,%2,%3}, {%4,%5,%6,%7}, {%8,%9}, {%0,%1,%2,%3};"
        : "+f"(d[0]), "+f"(d[1]), "+f"(d[2]), "+f"(d[3])
        : "r"(a[0]), "r"(a[1]), "r"(a[2]), "r"(a[3]), "r"(b0), "r"(b1));
}
__device__ __forceinline__ uint32_t pack2(float a, float b) {
    __half2 h = __floats2half2_rn(a, b);
    return *reinterpret_cast<uint32_t*>(&h);
}

// ---------------------------------------------------------------------------
// prep kernels
// ---------------------------------------------------------------------------
__global__ void cvt_h(const float* __restrict__ in, __half* __restrict__ out, int n4) {
    int i = blockIdx.x * blockDim.x + threadIdx.x;
    if (i < n4) {
        float4 v = ((const float4*)in)[i];
        uint2 u;
        u.x = pack2(v.x, v.y);
        u.y = pack2(v.z, v.w);
        ((uint2*)out)[i] = u;
    }
}

// out[c][r] = (half)in[r][c] ; R rows, C cols (both %32==0)
__global__ void tr_h(const float* __restrict__ in, __half* __restrict__ out,
                     int R, int C) {
    __shared__ float tile[32][33];
    const int c0 = blockIdx.x * 32, r0 = blockIdx.y * 32;
    for (int j = threadIdx.y; j < 32; j += 8)
        tile[j][threadIdx.x] = in[(size_t)(r0 + j) * C + c0 + threadIdx.x];
    __syncthreads();
    for (int j = threadIdx.y; j < 32; j += 8)
        out[(size_t)(c0 + j) * R + r0 + threadIdx.x] =
            __float2half_rn(tile[threadIdx.x][j]);
}

// ---------------------------------------------------------------------------
// fp16 GEMM: C[M,N] = A[M,K]h @ Bt[N,K]h^T + bias
// BM=128, BN=128, BK=64 halfs. 256 thr / 8 warps (2m x 4n), warp 64x32.
// Rows padded to 144B (9 granules) -> ldmatrix conflict-free.
// OUTH=1: fp16 out, cols<768 scaled by 0.125 (q). OUTH=0: fp32 out.
// ---------------------------------------------------------------------------
#define GROW 144
#define GST  36864   // bytes per stage: A(128*144) + B(128*144)
#define GDSM (2*GST)

__device__ __forceinline__ void g_stage(
    const __half* __restrict__ A, const __half* __restrict__ Bt,
    uint32_t as, uint32_t bs, int m0, int n0, int k0, int K, int tid)
{
    const int r = tid >> 3, c = tid & 7;
    const __half* Ap = A + (size_t)(m0 + r) * K + k0 + c * 8;
    const __half* Bp = Bt + (size_t)(n0 + r) * K + k0 + c * 8;
    #pragma unroll
    for (int p = 0; p < 4; p++) {
        cp16(as + (r + p * 32) * GROW + c * 16, Ap + (size_t)(p * 32) * K);
        cp16(bs + (r + p * 32) * GROW + c * 16, Bp + (size_t)(p * 32) * K);
    }
}

template<int OUTH>
__global__ __launch_bounds__(256) void gemm_h(
    const __half* __restrict__ A, const __half* __restrict__ Bt,
    const float* __restrict__ bias, void* __restrict__ Cout,
    int M, int N, int K)
{
    extern __shared__ char sm[];
    const uint32_t sbase = smem_u32(sm);
    const int tid = threadIdx.x, warp = tid >> 5, lane = tid & 31;
    const int g = lane >> 2, t = lane & 3;
    const int wm = (warp >> 2) * 64, wn = (warp & 3) * 32;
    const int m0 = blockIdx.y * 128, n0 = blockIdx.x * 128;

    float acc[4][4][4] = {};

    g_stage(A, Bt, sbase, sbase + 18432, m0, n0, 0, K, tid);
    CP_COMMIT;

    const int NCH = K / 64;
    for (int ch = 0; ch < NCH; ch++) {
        CP_WAIT0;
        __syncthreads();
        if (ch + 1 < NCH) {
            const uint32_t s = sbase + ((ch + 1) & 1) * GST;
            g_stage(A, Bt, s, s + 18432, m0, n0, (ch + 1) * 64, K, tid);
            CP_COMMIT;
        }
        const uint32_t as = sbase + (ch & 1) * GST;
        const uint32_t bs = as + 18432;
        #pragma unroll
        for (int j = 0; j < 4; j++) {
            const int kk = j * 16;
            uint32_t af[4][4];
            #pragma unroll
            for (int mi = 0; mi < 4; mi++)
                ldsm4(af[mi], as + (wm + mi * 16 + (lane & 15)) * GROW
                              + (kk + ((lane >> 4) << 3)) * 2);
            #pragma unroll
            for (int np = 0; np < 2; np++) {
                uint32_t bf[4];
                ldsm4(bf, bs + (wn + np * 16 + (lane & 7) + ((lane >> 4) << 3)) * GROW
                          + (kk + (((lane >> 3) & 1) << 3)) * 2);
                #pragma unroll
                for (int mi = 0; mi < 4; mi++) {
                    mma16(acc[mi][np * 2],     af[mi], bf[0], bf[1]);
                    mma16(acc[mi][np * 2 + 1], af[mi], bf[2], bf[3]);
                }
            }
        }
        __syncthreads();
    }

    #pragma unroll
    for (int mi = 0; mi < 4; mi++) {
        const int row = m0 + wm + mi * 16 + g;
        #pragma unroll
        for (int nb = 0; nb < 4; nb++) {
            const int col = n0 + wn + nb * 8 + 2 * t;
            const float b0 = bias[col], b1 = bias[col + 1];
            if (OUTH) {
                const float sc = (col < DD) ? 0.125f : 1.0f;
                __half* C = (__half*)Cout;
                *(uint32_t*)(C + (size_t)row * N + col) =
                    pack2((acc[mi][nb][0] + b0) * sc, (acc[mi][nb][1] + b1) * sc);
                *(uint32_t*)(C + (size_t)(row + 8) * N + col) =
                    pack2((acc[mi][nb][2] + b0) * sc, (acc[mi][nb][3] + b1) * sc);
            } else {
                float* C = (float*)Cout;
                *(float2*)(C + (size_t)row * N + col) =
                    make_float2(acc[mi][nb][0] + b0, acc[mi][nb][1] + b1);
                *(float2*)(C + (size_t)(row + 8) * N + col) =
                    make_float2(acc[mi][nb][2] + b0, acc[mi][nb][3] + b1);
            }
        }
    }
}

// ---------------------------------------------------------------------------
// fp16 causal flash attention. Grid (L/128, H, B), 256 thr / 8 warps.
// Q-tile 128 rows (16/warp, frags in regs, pre-scaled), K/V 64-row tiles,
// cp.async double-buffered. P stays in registers (C-frag -> A-frag repack).
// ---------------------------------------------------------------------------
#define FROW 144
#define FST  18432   // K(64*144) + V(64*144)
#define FDSM (2*FST)

__global__ __launch_bounds__(256) void flash_h(
    const __half* __restrict__ qkv, __half* __restrict__ y)
{
    extern __shared__ char sm[];
    const uint32_t sbase = smem_u32(sm);
    const int tid = threadIdx.x, warp = tid >> 5, lane = tid & 31;
    const int g = lane >> 2, t = lane & 3;
    const int qt = (int)gridDim.x - 1 - (int)blockIdx.x;  // big tiles first
    const int h = blockIdx.y, b = blockIdx.z;
    const int qbase = qt * 128, wrow = warp * 16;

    const __half* __restrict__ Qg = qkv + (size_t)b * LL * QKV_N + h * DH;
    const __half* __restrict__ Kg = qkv + (size_t)b * LL * QKV_N + DD + h * DH;
    const __half* __restrict__ Vg = qkv + (size_t)b * LL * QKV_N + 2 * DD + h * DH;

    // stage Q [128][72h] into stage-0 region, lift frags to regs
    #pragma unroll
    for (int p = 0; p < 4; p++) {
        const int id = p * 256 + tid;
        const int r = id >> 3, c = id & 7;
        cp16(sbase + r * FROW + c * 16, Qg + (size_t)(qbase + r) * QKV_N + c * 8);
    }
    CP_COMMIT; CP_WAIT0;
    __syncthreads();
    uint32_t qf[4][4];
    #pragma unroll
    for (int j = 0; j < 4; j++)
        ldsm4(qf[j], sbase + (wrow + (lane & 15)) * FROW
                     + (j * 16 + ((lane >> 4) << 3)) * 2);
    __syncthreads();

    float o[8][4] = {};
    float m_lo = -FLT_MAX, m_hi = -FLT_MAX, l_lo = 0.f, l_hi = 0.f;
    const int ktmax = 2 * (qt + 1);

    // stage kt=0
    #pragma unroll
    for (int p = 0; p < 2; p++) {
        const int id = p * 256 + tid;
        const int r = id >> 3, c = id & 7;
        cp16(sbase + r * FROW + c * 16, Kg + (size_t)r * QKV_N + c * 8);
        cp16(sbase + 9216 + r * FROW + c * 16, Vg + (size_t)r * QKV_N + c * 8);
    }
    CP_COMMIT;

    for (int kt = 0; kt < ktmax; kt++) {
        CP_WAIT0;
        __syncthreads();
        if (kt + 1 < ktmax) {
            const uint32_t s = sbase + ((kt + 1) & 1) * FST;
            const int nb = (kt + 1) * 64;
            #pragma unroll
            for (int p = 0; p < 2; p++) {
                const int id = p * 256 + tid;
                const int r = id >> 3, c = id & 7;
                cp16(s + r * FROW + c * 16, Kg + (size_t)(nb + r) * QKV_N + c * 8);
                cp16(s + 9216 + r * FROW + c * 16, Vg + (size_t)(nb + r) * QKV_N + c * 8);
            }
            CP_COMMIT;
        }
        const int kbase = kt * 64;
        if (kbase <= qbase + wrow + 15) {
            const uint32_t ks = sbase + (kt & 1) * FST;
            const uint32_t vs = ks + 9216;

            // S = Q @ K^T
            float s[8][4] = {};
            #pragma unroll
            for (int j = 0; j < 4; j++) {
                const int kk = j * 16;
                #pragma unroll
                for (int np = 0; np < 4; np++) {
                    uint32_t bf[4];
                    ldsm4(bf, ks + (np * 16 + (lane & 7) + ((lane >> 4) << 3)) * FROW
                              + (kk + (((lane >> 3) & 1) << 3)) * 2);
                    mma16(s[np * 2],     qf[j], bf[0], bf[1]);
                    mma16(s[np * 2 + 1], qf[j], bf[2], bf[3]);
                }
            }

            // causal mask (scale already folded into q)
            if (kbase + 63 > qbase + wrow) {
                const int row_lo = qbase + wrow + g, row_hi = row_lo + 8;
                #pragma unroll
                for (int n = 0; n < 8; n++) {
                    const int c0 = kbase + n * 8 + 2 * t;
                    if (c0 > row_lo)     s[n][0] = -FLT_MAX;
                    if (c0 + 1 > row_lo) s[n][1] = -FLT_MAX;
                    if (c0 > row_hi)     s[n][2] = -FLT_MAX;
                    if (c0 + 1 > row_hi) s[n][3] = -FLT_MAX;
                }
            }

            // online softmax (quad = 4 lanes of one row-pair)
            float mt_lo = -FLT_MAX, mt_hi = -FLT_MAX;
            #pragma unroll
            for (int n = 0; n < 8; n++) {
                mt_lo = fmaxf(mt_lo, fmaxf(s[n][0], s[n][1]));
                mt_hi = fmaxf(mt_hi, fmaxf(s[n][2], s[n][3]));
            }
            mt_lo = fmaxf(mt_lo, __shfl_xor_sync(0xffffffffu, mt_lo, 1));
            mt_lo = fmaxf(mt_lo, __shfl_xor_sync(0xffffffffu, mt_lo, 2));
            mt_hi = fmaxf(mt_hi, __shfl_xor_sync(0xffffffffu, mt_hi, 1));
            mt_hi = fmaxf(mt_hi, __shfl_xor_sync(0xffffffffu, mt_hi, 2));

            const float mn_lo = fmaxf(m_lo, mt_lo);
            const float mn_hi = fmaxf(m_hi, mt_hi);
            const float a_lo = __expf(m_lo - mn_lo);
            const float a_hi = __expf(m_hi - mn_hi);
            m_lo = mn_lo; m_hi = mn_hi;

            float sum_lo = 0.f, sum_hi = 0.f;
            #pragma unroll
            for (int n = 0; n < 8; n++) {
                s[n][0] = __expf(s[n][0] - m_lo);
                s[n][1] = __expf(s[n][1] - m_lo);
                s[n][2] = __expf(s[n][2] - m_hi);
                s[n][3] = __expf(s[n][3] - m_hi);
                sum_lo += s[n][0] + s[n][1];
                sum_hi += s[n][2] + s[n][3];
            }
            sum_lo += __shfl_xor_sync(0xffffffffu, sum_lo, 1);
            sum_lo += __shfl_xor_sync(0xffffffffu, sum_lo, 2);
            sum_hi += __shfl_xor_sync(0xffffffffu, sum_hi, 1);
            sum_hi += __shfl_xor_sync(0xffffffffu, sum_hi, 2);
            l_lo = l_lo * a_lo + sum_lo;
            l_hi = l_hi * a_hi + sum_hi;

            #pragma unroll
            for (int n = 0; n < 8; n++) {
                o[n][0] *= a_lo; o[n][1] *= a_lo;
                o[n][2] *= a_hi; o[n][3] *= a_hi;
            }

            // O += P @ V : P A-frags straight from S C-frags (register repack)
            #pragma unroll
            for (int j = 0; j < 4; j++) {
                uint32_t pa[4];
                pa[0] = pack2(s[2 * j][0],     s[2 * j][1]);
                pa[1] = pack2(s[2 * j][2],     s[2 * j][3]);
                pa[2] = pack2(s[2 * j + 1][0], s[2 * j + 1][1]);
                pa[3] = pack2(s[2 * j + 1][2], s[2 * j + 1][3]);
                const int kk = j * 16;
                #pragma unroll
                for (int np = 0; np < 4; np++) {
                    uint32_t bf[4];
                    ldsm4t(bf, vs + (kk + (lane & 7) + (((lane >> 3) & 1) << 3)) * FROW
                               + (np * 16 + ((lane >> 4) << 3)) * 2);
                    mma16(o[np * 2],     pa, bf[0], bf[1]);
                    mma16(o[np * 2 + 1], pa, bf[2], bf[3]);
                }
            }
        }
    }

    const float il_lo = 1.0f / l_lo;
    const float il_hi = 1.0f / l_hi;
    const int row = qbase + wrow + g;
    #pragma unroll
    for (int n = 0; n < 8; n++) {
        const int col = h * DH + n * 8 + 2 * t;
        *(uint32_t*)(y + ((size_t)b * LL + row) * DD + col) =
            pack2(o[n][0] * il_lo, o[n][1] * il_lo);
        *(uint32_t*)(y + ((size_t)b * LL + row + 8) * DD + col) =
            pack2(o[n][2] * il_hi, o[n][3] * il_hi);
    }
}

// ---------------------------------------------------------------------------
extern "C" void kernel_launch(void* const* d_in, const int* in_sizes, int n_in,
                              void* d_out, int out_size)
{
    (void)in_sizes; (void)n_in; (void)out_size;
    const float* x    = (const float*)d_in[0];
    const float* Wqkv = (const float*)d_in[1];
    const float* bqkv = (const float*)d_in[2];
    const float* Wo   = (const float*)d_in[3];
    const float* bo   = (const float*)d_in[4];
    float* out = (float*)d_out;

    __half *xh, *wqkvt, *wot, *qkvh, *yh;
    cudaGetSymbolAddress((void**)&xh, g_xh);
    cudaGetSymbolAddress((void**)&wqkvt, g_wqkvt);
    cudaGetSymbolAddress((void**)&wot, g_wot);
    cudaGetSymbolAddress((void**)&qkvh, g_qkvh);
    cudaGetSymbolAddress((void**)&yh, g_yh);

    static bool attr_done = false;
    if (!attr_done) {
        cudaFuncSetAttribute(gemm_h<1>, cudaFuncAttributeMaxDynamicSharedMemorySize, GDSM);
        cudaFuncSetAttribute(gemm_h<0>, cudaFuncAttributeMaxDynamicSharedMemorySize, GDSM);
        cudaFuncSetAttribute(flash_h, cudaFuncAttributeMaxDynamicSharedMemorySize, FDSM);
        attr_done = true;
    }

    // prep: fp16 x, transposed fp16 weights
    cvt_h<<<(MM * DD / 4 + 255) / 256, 256>>>(x, xh, MM * DD / 4);
    tr_h<<<dim3(QKV_N / 32, DD / 32), dim3(32, 8)>>>(Wqkv, wqkvt, DD, QKV_N);
    tr_h<<<dim3(DD / 32, DD / 32), dim3(32, 8)>>>(Wo, wot, DD, DD);

    gemm_h<1><<<dim3(QKV_N / 128, MM / 128), 256, GDSM>>>(
        xh, wqkvt, bqkv, qkvh, MM, QKV_N, DD);

    flash_h<<<dim3(LL / 128, HH, BB), 256, FDSM>>>(qkvh, yh);

    gemm_h<0><<<dim3(DD / 128, MM / 128), 256, GDSM>>>(
        yh, wot, bo, out, MM, DD, DD);
}